// round 3
// baseline (speedup 1.0000x reference)
#include <cuda_runtime.h>
#include <math.h>

#define VSZ 5000
#define HSZ 1024
#define ESZ 512
#define BSZ 64
#define TSZ 256
#define H4  (4 * HSZ)
#define MROWS (BSZ * TSZ)   // 16384
#define NBLK 128
#define KP 20               // Hs padded k-stride
#define WPAD 1028           // Wsm padded k-stride (conflict-free fragment loads)

// ---------------- scratch ---------------------------------------------------
__device__ float g_x [(size_t)MROWS * ESZ];
__device__ float g_xg[(size_t)MROWS * H4];
__device__ float g_h1[(size_t)MROWS * HSZ];
__device__ float g_h2[(size_t)MROWS * HSZ];
__device__ unsigned g_ctr[2 * TSZ];   // per-layer, per-step barrier counters

// ---------------- tf32 helpers ---------------------------------------------
__device__ __forceinline__ unsigned f2tf(float x) {
    unsigned u; asm("cvt.rna.tf32.f32 %0, %1;" : "=r"(u) : "f"(x)); return u;
}
__device__ __forceinline__ void mma8(float* c, const unsigned* a, const unsigned* b) {
    asm volatile(
        "mma.sync.aligned.m16n8k8.row.col.f32.tf32.tf32.f32 "
        "{%0,%1,%2,%3}, {%4,%5,%6,%7}, {%8,%9}, {%0,%1,%2,%3};\n"
        : "+f"(c[0]), "+f"(c[1]), "+f"(c[2]), "+f"(c[3])
        : "r"(a[0]), "r"(a[1]), "r"(a[2]), "r"(a[3]), "r"(b[0]), "r"(b[1]));
}

// ---------------- misc small kernels ----------------------------------------
__global__ void zero_ctr_kernel() { g_ctr[threadIdx.x] = 0u; }

__global__ void embed_kernel(const int* __restrict__ input,
                             const float* __restrict__ embed_W)
{
    int row = blockIdx.x;
    int idx = input[row];
    const float4* src = (const float4*)(embed_W + (size_t)idx * ESZ);
    float4* dst = (float4*)(g_x + (size_t)row * ESZ);
    dst[threadIdx.x] = src[threadIdx.x];
}

// ---------------- tf32 tensor GEMM: C = A(MxK) @ W(NxK)^T + b0 (+ b1) ------
// BM=128, BN=64, BK=16, 256 threads (8 warps as 4m x 2n, warp tile 32x32)
__global__ void __launch_bounds__(256, 2)
tgemm(const float* __restrict__ A, const float* __restrict__ W,
      const float* __restrict__ b0v, const float* __restrict__ b1v,
      float* __restrict__ C, int M, int N, int K)
{
    __shared__ unsigned As[2][128][KP];
    __shared__ unsigned Ws[2][64][KP];

    const int tid = threadIdx.x, lane = tid & 31, wid = tid >> 5;
    const int m0 = blockIdx.y * 128, n0 = blockIdx.x * 64;
    const int wm = (wid >> 1) * 32, wn = (wid & 1) * 32;
    const int r = lane >> 2, q = lane & 3;

    float acc[2][4][4];
    #pragma unroll
    for (int i = 0; i < 2; i++)
        #pragma unroll
        for (int j = 0; j < 4; j++)
            #pragma unroll
            for (int k = 0; k < 4; k++) acc[i][j][k] = 0.f;

    const int NIT = K / 16;

    float4 aR[2]; float4 bR;
    const int arow0 = tid >> 2;
    const int akg   = (tid & 3) * 4;
    const int bnl   = tid >> 2;
    const int wrow  = n0 + bnl;
    const bool wok  = (wrow < N);

    {
        aR[0] = *(const float4*)&A[(size_t)(m0 + arow0) * K + akg];
        aR[1] = *(const float4*)&A[(size_t)(m0 + 64 + arow0) * K + akg];
        bR = wok ? *(const float4*)&W[(size_t)wrow * K + akg] : make_float4(0,0,0,0);
        unsigned* s0 = &As[0][arow0][akg];
        s0[0]=f2tf(aR[0].x); s0[1]=f2tf(aR[0].y); s0[2]=f2tf(aR[0].z); s0[3]=f2tf(aR[0].w);
        unsigned* s1 = &As[0][64 + arow0][akg];
        s1[0]=f2tf(aR[1].x); s1[1]=f2tf(aR[1].y); s1[2]=f2tf(aR[1].z); s1[3]=f2tf(aR[1].w);
        unsigned* sw = &Ws[0][bnl][akg];
        sw[0]=f2tf(bR.x); sw[1]=f2tf(bR.y); sw[2]=f2tf(bR.z); sw[3]=f2tf(bR.w);
    }
    __syncthreads();

    for (int it = 0; it < NIT; ++it) {
        if (it + 1 < NIT) {
            int k0 = (it + 1) * 16;
            aR[0] = *(const float4*)&A[(size_t)(m0 + arow0) * K + k0 + akg];
            aR[1] = *(const float4*)&A[(size_t)(m0 + 64 + arow0) * K + k0 + akg];
            bR = wok ? *(const float4*)&W[(size_t)wrow * K + k0 + akg] : make_float4(0,0,0,0);
        }
        const int bf = it & 1;
        #pragma unroll
        for (int kc = 0; kc < 16; kc += 8) {
            unsigned af[2][4];
            #pragma unroll
            for (int tm = 0; tm < 2; tm++) {
                af[tm][0] = As[bf][wm + tm*16 + r    ][kc + q];
                af[tm][1] = As[bf][wm + tm*16 + r + 8][kc + q];
                af[tm][2] = As[bf][wm + tm*16 + r    ][kc + q + 4];
                af[tm][3] = As[bf][wm + tm*16 + r + 8][kc + q + 4];
            }
            unsigned bg[4][2];
            #pragma unroll
            for (int tn = 0; tn < 4; tn++) {
                bg[tn][0] = Ws[bf][wn + tn*8 + r][kc + q];
                bg[tn][1] = Ws[bf][wn + tn*8 + r][kc + q + 4];
            }
            #pragma unroll
            for (int tm = 0; tm < 2; tm++)
                #pragma unroll
                for (int tn = 0; tn < 4; tn++)
                    mma8(acc[tm][tn], af[tm], bg[tn]);
        }
        if (it + 1 < NIT) {
            const int nb = (it + 1) & 1;
            unsigned* s0 = &As[nb][arow0][akg];
            s0[0]=f2tf(aR[0].x); s0[1]=f2tf(aR[0].y); s0[2]=f2tf(aR[0].z); s0[3]=f2tf(aR[0].w);
            unsigned* s1 = &As[nb][64 + arow0][akg];
            s1[0]=f2tf(aR[1].x); s1[1]=f2tf(aR[1].y); s1[2]=f2tf(aR[1].z); s1[3]=f2tf(aR[1].w);
            unsigned* sw = &Ws[nb][bnl][akg];
            sw[0]=f2tf(bR.x); sw[1]=f2tf(bR.y); sw[2]=f2tf(bR.z); sw[3]=f2tf(bR.w);
        }
        __syncthreads();
    }

    #pragma unroll
    for (int tm = 0; tm < 2; tm++) {
        #pragma unroll
        for (int tn = 0; tn < 4; tn++) {
            int n = n0 + wn + tn*8 + 2*q;
            float bb0 = 0.f, bb1 = 0.f;
            if (n < N)     bb0 = b0v[n]     + (b1v ? b1v[n]     : 0.f);
            if (n + 1 < N) bb1 = b0v[n + 1] + (b1v ? b1v[n + 1] : 0.f);
            int m = m0 + wm + tm*16 + r;
            if (n < N) {
                C[(size_t)m * N + n]       = acc[tm][tn][0] + bb0;
                C[(size_t)(m+8) * N + n]   = acc[tm][tn][2] + bb0;
            }
            if (n + 1 < N) {
                C[(size_t)m * N + n + 1]     = acc[tm][tn][1] + bb1;
                C[(size_t)(m+8) * N + n + 1] = acc[tm][tn][3] + bb1;
            }
        }
    }
}

// ---------------- persistent LSTM layer -------------------------------------
// 128 blocks (1/SM), 256 threads. Block owns 32 gate cols (8 h-units x 4 gates).
// W_hh slice lives in SMEM (tf32) for the whole layer. 256 timesteps internally,
// separated by a global arrive/spin barrier (per-step counters).
// Cell state kept in registers (2 elems/thread).
__global__ void __launch_bounds__(256, 1)
lstm_persist(const float* __restrict__ Xg,   // (B*T, 4H), biases baked in
             const float* __restrict__ Whh,  // (4H, H)
             float* __restrict__ h_all,      // (B*T, H)
             unsigned* __restrict__ ctr)     // [TSZ]
{
    extern __shared__ unsigned smp[];
    unsigned* Wsm = smp;                           // [32][WPAD]
    unsigned* Hsb = Wsm + 32 * WPAD;               // [2][2][64][KP]
    float*    Gb  = (float*)(Hsb + 2*2*64*KP);     // [2][64][33]

    const int tid = threadIdx.x, lane = tid & 31, wid = tid >> 5;
    const int h0 = blockIdx.x * 8;
    const int mw = wid & 3, kh = wid >> 2;
    const int r = lane >> 2, q = lane & 3;

    // ---- load W slice into SMEM (tf32), once ----
    {
        int n  = tid >> 3;                       // 0..31 local gate col
        int kb = (tid & 7) * 128;                // k base
        int wrow = ((n >> 3) * HSZ) + h0 + (n & 7);
        const float4* src = (const float4*)&Whh[(size_t)wrow * HSZ + kb];
        unsigned* dst = &Wsm[n * WPAD + kb];
        #pragma unroll
        for (int i = 0; i < 32; i++) {
            float4 v = src[i];
            dst[i*4+0]=f2tf(v.x); dst[i*4+1]=f2tf(v.y);
            dst[i*4+2]=f2tf(v.z); dst[i*4+3]=f2tf(v.w);
        }
    }
    __syncthreads();

    float cr0 = 0.f, cr1 = 0.f;                  // persistent cell state
    const int hrow = tid >> 2;                   // 0..63 (batch row)
    const int kg   = (tid & 3) * 4;
    const int bb0i = tid >> 3, jj = tid & 7;     // epilogue mapping

    volatile unsigned* vctr = ctr;

    for (int t = 0; t < TSZ; t++) {
        float acc[4][4];
        #pragma unroll
        for (int i = 0; i < 4; i++)
            #pragma unroll
            for (int j = 0; j < 4; j++) acc[i][j] = 0.f;

        if (t > 0) {
            // wait for all blocks to finish step t-1
            if (tid == 0) {
                while (vctr[t-1] < NBLK) { }
                __threadfence();
            }
            __syncthreads();

            const float* hbase = &h_all[((size_t)hrow * TSZ + (t - 1)) * HSZ];

            // prologue: stage chunk 0 (both k-halves)
            {
                float4 a0 = *(const float4*)&hbase[kg];
                float4 a1 = *(const float4*)&hbase[512 + kg];
                unsigned* p0 = &Hsb[((0*2 + 0)*64 + hrow)*KP + kg];
                p0[0]=f2tf(a0.x); p0[1]=f2tf(a0.y); p0[2]=f2tf(a0.z); p0[3]=f2tf(a0.w);
                unsigned* p1 = &Hsb[((0*2 + 1)*64 + hrow)*KP + kg];
                p1[0]=f2tf(a1.x); p1[1]=f2tf(a1.y); p1[2]=f2tf(a1.z); p1[3]=f2tf(a1.w);
            }
            __syncthreads();

            for (int it = 0; it < 32; ++it) {
                float4 n0v, n1v;
                if (it + 1 < 32) {
                    int k0 = (it + 1) * 16;
                    n0v = *(const float4*)&hbase[k0 + kg];
                    n1v = *(const float4*)&hbase[512 + k0 + kg];
                }
                const int bf = it & 1;
                const unsigned* hs = &Hsb[((bf*2 + kh)*64)*KP];
                #pragma unroll
                for (int kc = 0; kc < 16; kc += 8) {
                    unsigned af[4];
                    af[0] = hs[(mw*16 + r    )*KP + kc + q];
                    af[1] = hs[(mw*16 + r + 8)*KP + kc + q];
                    af[2] = hs[(mw*16 + r    )*KP + kc + q + 4];
                    af[3] = hs[(mw*16 + r + 8)*KP + kc + q + 4];
                    const int kabs = kh*512 + it*16 + kc;
                    #pragma unroll
                    for (int tn = 0; tn < 4; tn++) {
                        unsigned bg[2];
                        bg[0] = Wsm[(tn*8 + r)*WPAD + kabs + q];
                        bg[1] = Wsm[(tn*8 + r)*WPAD + kabs + q + 4];
                        mma8(acc[tn], af, bg);
                    }
                }
                if (it + 1 < 32) {
                    const int nb = (it + 1) & 1;
                    unsigned* p0 = &Hsb[((nb*2 + 0)*64 + hrow)*KP + kg];
                    p0[0]=f2tf(n0v.x); p0[1]=f2tf(n0v.y); p0[2]=f2tf(n0v.z); p0[3]=f2tf(n0v.w);
                    unsigned* p1 = &Hsb[((nb*2 + 1)*64 + hrow)*KP + kg];
                    p1[0]=f2tf(n1v.x); p1[1]=f2tf(n1v.y); p1[2]=f2tf(n1v.z); p1[3]=f2tf(n1v.w);
                }
                __syncthreads();
            }
        }

        // stage accumulators (per k-half) to SMEM
        #pragma unroll
        for (int tn = 0; tn < 4; tn++) {
            int col = tn*8 + 2*q;
            float* gb = &Gb[kh*64*33];
            gb[(mw*16 + r    )*33 + col]     = acc[tn][0];
            gb[(mw*16 + r    )*33 + col + 1] = acc[tn][1];
            gb[(mw*16 + r + 8)*33 + col]     = acc[tn][2];
            gb[(mw*16 + r + 8)*33 + col + 1] = acc[tn][3];
        }
        __syncthreads();

        // cell update: 2 (b, j) elems per thread; c in registers
        #pragma unroll
        for (int half = 0; half < 2; half++) {
            int b = bb0i + half * 32;
            size_t xb = ((size_t)b * TSZ + t) * H4;
            float iv = Gb[b*33 + jj]            + Gb[(64 + b)*33 + jj]            + Xg[xb + 0*HSZ + h0 + jj];
            float fv = Gb[b*33 + 8 + jj]        + Gb[(64 + b)*33 + 8 + jj]        + Xg[xb + 1*HSZ + h0 + jj];
            float gv = Gb[b*33 + 16 + jj]       + Gb[(64 + b)*33 + 16 + jj]       + Xg[xb + 2*HSZ + h0 + jj];
            float ov = Gb[b*33 + 24 + jj]       + Gb[(64 + b)*33 + 24 + jj]       + Xg[xb + 3*HSZ + h0 + jj];
            float cp = half ? cr1 : cr0;
            float si = 1.f / (1.f + expf(-iv));
            float sf = 1.f / (1.f + expf(-fv));
            float so = 1.f / (1.f + expf(-ov));
            float cn = sf * cp + si * tanhf(gv);
            float hn = so * tanhf(cn);
            if (half) cr1 = cn; else cr0 = cn;
            h_all[((size_t)b * TSZ + t) * HSZ + h0 + jj] = hn;
        }

        __threadfence();
        __syncthreads();
        if (tid == 0) atomicAdd(&ctr[t], 1u);
    }
}

// ---------------- launch ----------------------------------------------------
#define SMEM_PERSIST ((32*WPAD + 2*2*64*KP) * 4 + 2*64*33*4)

extern "C" void kernel_launch(void* const* d_in, const int* in_sizes, int n_in,
                              void* d_out, int out_size)
{
    const int*   input  = (const int*)  d_in[0];
    const float* embedW = (const float*)d_in[2];
    const float* W_ih1  = (const float*)d_in[3];
    const float* W_hh1  = (const float*)d_in[4];
    const float* b_ih1  = (const float*)d_in[5];
    const float* b_hh1  = (const float*)d_in[6];
    const float* W_ih2  = (const float*)d_in[7];
    const float* W_hh2  = (const float*)d_in[8];
    const float* b_ih2  = (const float*)d_in[9];
    const float* b_hh2  = (const float*)d_in[10];
    const float* lin_W  = (const float*)d_in[11];
    const float* lin_b  = (const float*)d_in[12];
    float* out = (float*)d_out;

    float *x, *xg, *h1, *h2; unsigned* ctr;
    cudaGetSymbolAddress((void**)&x,   g_x);
    cudaGetSymbolAddress((void**)&xg,  g_xg);
    cudaGetSymbolAddress((void**)&h1,  g_h1);
    cudaGetSymbolAddress((void**)&h2,  g_h2);
    cudaGetSymbolAddress((void**)&ctr, g_ctr);

    cudaFuncSetAttribute(lstm_persist,
                         cudaFuncAttributeMaxDynamicSharedMemorySize, SMEM_PERSIST);

    zero_ctr_kernel<<<1, 2 * TSZ>>>();
    embed_kernel<<<MROWS, 128>>>(input, embedW);

    {   // Xg1 = x @ W_ih1^T + b_ih1 + b_hh1
        dim3 grid(H4 / 64, MROWS / 128);
        tgemm<<<grid, 256>>>(x, W_ih1, b_ih1, b_hh1, xg, MROWS, H4, ESZ);
    }
    lstm_persist<<<NBLK, 256, SMEM_PERSIST>>>(xg, W_hh1, h1, ctr);

    {   // Xg2 = h1 @ W_ih2^T + b_ih2 + b_hh2
        dim3 grid(H4 / 64, MROWS / 128);
        tgemm<<<grid, 256>>>(h1, W_ih2, b_ih2, b_hh2, xg, MROWS, H4, HSZ);
    }
    lstm_persist<<<NBLK, 256, SMEM_PERSIST>>>(xg, W_hh2, h2, ctr + TSZ);

    {   // outs = h2 @ lin_W^T + lin_b
        dim3 grid((VSZ + 63) / 64, MROWS / 128);
        tgemm<<<grid, 256>>>(h2, lin_W, lin_b, nullptr, out, MROWS, VSZ, HSZ);
    }
}

// round 4
// speedup vs baseline: 1.7610x; 1.7610x over previous
#include <cuda_runtime.h>
#include <math.h>

#define VSZ 5000
#define HSZ 1024
#define ESZ 512
#define BSZ 64
#define TSZ 256
#define H4  (4 * HSZ)
#define MROWS (BSZ * TSZ)   // 16384
#define NBLK 128
#define KP 20               // tgemm padded k-stride

// ---------------- scratch ---------------------------------------------------
__device__ float g_x [(size_t)MROWS * ESZ];
__device__ float g_xg[(size_t)MROWS * H4];
__device__ float g_h1[(size_t)MROWS * HSZ];
__device__ float g_h2[(size_t)MROWS * HSZ];
__device__ float g_hfrag[2][BSZ * HSZ];   // tf32-packed A fragments, double buffered
__device__ unsigned g_ctr[2 * TSZ];

// ---------------- tf32 helpers ---------------------------------------------
__device__ __forceinline__ unsigned f2tf(float x) {
    unsigned u; asm("cvt.rna.tf32.f32 %0, %1;" : "=r"(u) : "f"(x)); return u;
}
__device__ __forceinline__ void mma8(float* c, const unsigned* a, const unsigned* b) {
    asm volatile(
        "mma.sync.aligned.m16n8k8.row.col.f32.tf32.tf32.f32 "
        "{%0,%1,%2,%3}, {%4,%5,%6,%7}, {%8,%9}, {%0,%1,%2,%3};\n"
        : "+f"(c[0]), "+f"(c[1]), "+f"(c[2]), "+f"(c[3])
        : "r"(a[0]), "r"(a[1]), "r"(a[2]), "r"(a[3]), "r"(b[0]), "r"(b[1]));
}

// ---------------- misc small kernels ----------------------------------------
__global__ void zero_ctr_kernel() { g_ctr[threadIdx.x] = 0u; }

__global__ void embed_kernel(const int* __restrict__ input,
                             const float* __restrict__ embed_W)
{
    int row = blockIdx.x;
    int idx = input[row];
    const float4* src = (const float4*)(embed_W + (size_t)idx * ESZ);
    float4* dst = (float4*)(g_x + (size_t)row * ESZ);
    dst[threadIdx.x] = src[threadIdx.x];
}

// ---------------- tf32 tensor GEMM (unchanged from r2) ----------------------
__global__ void __launch_bounds__(256, 2)
tgemm(const float* __restrict__ A, const float* __restrict__ W,
      const float* __restrict__ b0v, const float* __restrict__ b1v,
      float* __restrict__ C, int M, int N, int K)
{
    __shared__ unsigned As[2][128][KP];
    __shared__ unsigned Ws[2][64][KP];

    const int tid = threadIdx.x, lane = tid & 31, wid = tid >> 5;
    const int m0 = blockIdx.y * 128, n0 = blockIdx.x * 64;
    const int wm = (wid >> 1) * 32, wn = (wid & 1) * 32;
    const int r = lane >> 2, q = lane & 3;

    float acc[2][4][4];
    #pragma unroll
    for (int i = 0; i < 2; i++)
        #pragma unroll
        for (int j = 0; j < 4; j++)
            #pragma unroll
            for (int k = 0; k < 4; k++) acc[i][j][k] = 0.f;

    const int NIT = K / 16;

    float4 aR[2]; float4 bR;
    const int arow0 = tid >> 2;
    const int akg   = (tid & 3) * 4;
    const int bnl   = tid >> 2;
    const int wrow  = n0 + bnl;
    const bool wok  = (wrow < N);

    {
        aR[0] = *(const float4*)&A[(size_t)(m0 + arow0) * K + akg];
        aR[1] = *(const float4*)&A[(size_t)(m0 + 64 + arow0) * K + akg];
        bR = wok ? *(const float4*)&W[(size_t)wrow * K + akg] : make_float4(0,0,0,0);
        unsigned* s0 = &As[0][arow0][akg];
        s0[0]=f2tf(aR[0].x); s0[1]=f2tf(aR[0].y); s0[2]=f2tf(aR[0].z); s0[3]=f2tf(aR[0].w);
        unsigned* s1 = &As[0][64 + arow0][akg];
        s1[0]=f2tf(aR[1].x); s1[1]=f2tf(aR[1].y); s1[2]=f2tf(aR[1].z); s1[3]=f2tf(aR[1].w);
        unsigned* sw = &Ws[0][bnl][akg];
        sw[0]=f2tf(bR.x); sw[1]=f2tf(bR.y); sw[2]=f2tf(bR.z); sw[3]=f2tf(bR.w);
    }
    __syncthreads();

    for (int it = 0; it < NIT; ++it) {
        if (it + 1 < NIT) {
            int k0 = (it + 1) * 16;
            aR[0] = *(const float4*)&A[(size_t)(m0 + arow0) * K + k0 + akg];
            aR[1] = *(const float4*)&A[(size_t)(m0 + 64 + arow0) * K + k0 + akg];
            bR = wok ? *(const float4*)&W[(size_t)wrow * K + k0 + akg] : make_float4(0,0,0,0);
        }
        const int bf = it & 1;
        #pragma unroll
        for (int kc = 0; kc < 16; kc += 8) {
            unsigned af[2][4];
            #pragma unroll
            for (int tm = 0; tm < 2; tm++) {
                af[tm][0] = As[bf][wm + tm*16 + r    ][kc + q];
                af[tm][1] = As[bf][wm + tm*16 + r + 8][kc + q];
                af[tm][2] = As[bf][wm + tm*16 + r    ][kc + q + 4];
                af[tm][3] = As[bf][wm + tm*16 + r + 8][kc + q + 4];
            }
            unsigned bg[4][2];
            #pragma unroll
            for (int tn = 0; tn < 4; tn++) {
                bg[tn][0] = Ws[bf][wn + tn*8 + r][kc + q];
                bg[tn][1] = Ws[bf][wn + tn*8 + r][kc + q + 4];
            }
            #pragma unroll
            for (int tm = 0; tm < 2; tm++)
                #pragma unroll
                for (int tn = 0; tn < 4; tn++)
                    mma8(acc[tm][tn], af[tm], bg[tn]);
        }
        if (it + 1 < NIT) {
            const int nb = (it + 1) & 1;
            unsigned* s0 = &As[nb][arow0][akg];
            s0[0]=f2tf(aR[0].x); s0[1]=f2tf(aR[0].y); s0[2]=f2tf(aR[0].z); s0[3]=f2tf(aR[0].w);
            unsigned* s1 = &As[nb][64 + arow0][akg];
            s1[0]=f2tf(aR[1].x); s1[1]=f2tf(aR[1].y); s1[2]=f2tf(aR[1].z); s1[3]=f2tf(aR[1].w);
            unsigned* sw = &Ws[nb][bnl][akg];
            sw[0]=f2tf(bR.x); sw[1]=f2tf(bR.y); sw[2]=f2tf(bR.z); sw[3]=f2tf(bR.w);
        }
        __syncthreads();
    }

    #pragma unroll
    for (int tm = 0; tm < 2; tm++) {
        #pragma unroll
        for (int tn = 0; tn < 4; tn++) {
            int n = n0 + wn + tn*8 + 2*q;
            float bb0 = 0.f, bb1 = 0.f;
            if (n < N)     bb0 = b0v[n]     + (b1v ? b1v[n]     : 0.f);
            if (n + 1 < N) bb1 = b0v[n + 1] + (b1v ? b1v[n + 1] : 0.f);
            int m = m0 + wm + tm*16 + r;
            if (n < N) {
                C[(size_t)m * N + n]       = acc[tm][tn][0] + bb0;
                C[(size_t)(m+8) * N + n]   = acc[tm][tn][2] + bb0;
            }
            if (n + 1 < N) {
                C[(size_t)m * N + n + 1]     = acc[tm][tn][1] + bb1;
                C[(size_t)(m+8) * N + n + 1] = acc[tm][tn][3] + bb1;
            }
        }
    }
}

// ---------------- persistent LSTM layer, v2 ---------------------------------
// 128 blocks x 256 thr, 1/SM. Block owns 32 gate cols (8 h-units x 4 gates).
// W packed fragment-order in SMEM (once). A fragments read straight from
// g_hfrag (global, L2-resident) via LDG.128 — K-loop has NO syncthreads.
// Epilogue writes h as fp32 (h_all) and tf32 packed fragments (g_hfrag).
__global__ void __launch_bounds__(256, 1)
lstm_persist2(const float* __restrict__ Xg, const float* __restrict__ Whh,
              float* __restrict__ h_all, unsigned* __restrict__ ctr)
{
    extern __shared__ float smf[];
    float* Wp = smf;                 // [4tn][128c][32lane][2e] = 32768 floats
    float* Gb = smf + 32768;         // [2kh][64][33]

    const int tid = threadIdx.x, lane = tid & 31, wid = tid >> 5;
    const int h0 = blockIdx.x * 8;
    const int mw = wid & 3, kh = wid >> 2;
    const int r = lane >> 2, q = lane & 3;

    // ---- pack W slice into SMEM fragments (once) ----
    for (int idx = tid; idx < 32 * 1024; idx += 256) {
        int nl = idx >> 10, k = idx & 1023;
        int wrow = ((nl >> 3) * HSZ) + h0 + (nl & 7);
        float v = Whh[(size_t)wrow * HSZ + k];
        int tn = nl >> 3, rw = nl & 7;
        int c = k >> 3, e = (k & 7) >> 2, qq = k & 3;
        int ln = rw * 4 + qq;
        Wp[((size_t)(tn * 128 + c) * 32 + ln) * 2 + e] = __uint_as_float(f2tf(v));
    }
    __syncthreads();

    // epilogue / producer mapping
    const int bb0i = tid >> 3, jj = tid & 7;
    int pk[2]; size_t ha[2];
    #pragma unroll
    for (int half = 0; half < 2; half++) {
        int b = bb0i + 32 * half;
        int g = b >> 4, ml = b & 15;
        int ln = (ml & 7) * 4 + (jj & 3);
        int e  = (ml >> 3) + 2 * (jj >> 2);
        pk[half] = ((g * 128 + blockIdx.x) * 32 + ln) * 4 + e;
        ha[half] = ((size_t)b * TSZ) * HSZ + h0 + jj;   // + t*HSZ at use
    }

    float cr0 = 0.f, cr1 = 0.f;
    volatile unsigned* vctr = ctr;

    for (int t = 0; t < TSZ; t++) {
        // prefetch Xg for this step (independent of barrier)
        float xv[2][4];
        #pragma unroll
        for (int half = 0; half < 2; half++) {
            size_t xb = ((size_t)(bb0i + 32 * half) * TSZ + t) * H4 + h0 + jj;
            #pragma unroll
            for (int g4 = 0; g4 < 4; g4++) xv[half][g4] = Xg[xb + g4 * HSZ];
        }

        float acc[4][4];
        #pragma unroll
        for (int i = 0; i < 4; i++)
            #pragma unroll
            for (int j = 0; j < 4; j++) acc[i][j] = 0.f;

        if (t > 0) {
            if (tid == 0) { while (vctr[t - 1] < NBLK) { } }
            __syncthreads();
            __threadfence();

            const float* ab = g_hfrag[(t - 1) & 1] + (mw * 128 + kh * 64) * 128 + lane * 4;
            const float* wb = Wp + (size_t)(kh * 64) * 64 + lane * 2;

            #pragma unroll 8
            for (int cc = 0; cc < 64; cc++) {
                float4 a4 = *(const float4*)(ab + cc * 128);
                unsigned af[4] = { __float_as_uint(a4.x), __float_as_uint(a4.y),
                                   __float_as_uint(a4.z), __float_as_uint(a4.w) };
                #pragma unroll
                for (int tn = 0; tn < 4; tn++) {
                    float2 w2 = *(const float2*)(wb + ((size_t)tn * 128 + cc) * 64);
                    unsigned bg[2] = { __float_as_uint(w2.x), __float_as_uint(w2.y) };
                    mma8(acc[tn], af, bg);
                }
            }
        }

        // stage accumulators (per k-half) to SMEM
        #pragma unroll
        for (int tn = 0; tn < 4; tn++) {
            int col = tn * 8 + 2 * q;
            float* gb = &Gb[kh * 64 * 33];
            gb[(mw*16 + r    )*33 + col]     = acc[tn][0];
            gb[(mw*16 + r    )*33 + col + 1] = acc[tn][1];
            gb[(mw*16 + r + 8)*33 + col]     = acc[tn][2];
            gb[(mw*16 + r + 8)*33 + col + 1] = acc[tn][3];
        }
        __syncthreads();

        // cell update (c in registers), dual h write
        float* hfo = g_hfrag[t & 1];
        #pragma unroll
        for (int half = 0; half < 2; half++) {
            int b = bb0i + 32 * half;
            float iv = Gb[b*33 + jj]      + Gb[(64+b)*33 + jj]      + xv[half][0];
            float fv = Gb[b*33 + 8 + jj]  + Gb[(64+b)*33 + 8 + jj]  + xv[half][1];
            float gv = Gb[b*33 + 16 + jj] + Gb[(64+b)*33 + 16 + jj] + xv[half][2];
            float ov = Gb[b*33 + 24 + jj] + Gb[(64+b)*33 + 24 + jj] + xv[half][3];
            float cp = half ? cr1 : cr0;
            float si = 1.f / (1.f + expf(-iv));
            float sf = 1.f / (1.f + expf(-fv));
            float so = 1.f / (1.f + expf(-ov));
            float cn = sf * cp + si * tanhf(gv);
            float hn = so * tanhf(cn);
            if (half) cr1 = cn; else cr0 = cn;
            h_all[ha[half] + (size_t)t * HSZ] = hn;
            hfo[pk[half]] = __uint_as_float(f2tf(hn));
        }

        __threadfence();
        __syncthreads();
        if (tid == 0) atomicAdd(&ctr[t], 1u);
    }
}

// ---------------- launch ----------------------------------------------------
#define SMEM_P2 ((32768 + 2 * 64 * 33) * 4)

extern "C" void kernel_launch(void* const* d_in, const int* in_sizes, int n_in,
                              void* d_out, int out_size)
{
    const int*   input  = (const int*)  d_in[0];
    const float* embedW = (const float*)d_in[2];
    const float* W_ih1  = (const float*)d_in[3];
    const float* W_hh1  = (const float*)d_in[4];
    const float* b_ih1  = (const float*)d_in[5];
    const float* b_hh1  = (const float*)d_in[6];
    const float* W_ih2  = (const float*)d_in[7];
    const float* W_hh2  = (const float*)d_in[8];
    const float* b_ih2  = (const float*)d_in[9];
    const float* b_hh2  = (const float*)d_in[10];
    const float* lin_W  = (const float*)d_in[11];
    const float* lin_b  = (const float*)d_in[12];
    float* out = (float*)d_out;

    float *x, *xg, *h1, *h2; unsigned* ctr;
    cudaGetSymbolAddress((void**)&x,   g_x);
    cudaGetSymbolAddress((void**)&xg,  g_xg);
    cudaGetSymbolAddress((void**)&h1,  g_h1);
    cudaGetSymbolAddress((void**)&h2,  g_h2);
    cudaGetSymbolAddress((void**)&ctr, g_ctr);

    cudaFuncSetAttribute(lstm_persist2,
                         cudaFuncAttributeMaxDynamicSharedMemorySize, SMEM_P2);

    zero_ctr_kernel<<<1, 2 * TSZ>>>();
    embed_kernel<<<MROWS, 128>>>(input, embedW);

    {   // Xg1 = x @ W_ih1^T + b_ih1 + b_hh1
        dim3 grid(H4 / 64, MROWS / 128);
        tgemm<<<grid, 256>>>(x, W_ih1, b_ih1, b_hh1, xg, MROWS, H4, ESZ);
    }
    lstm_persist2<<<NBLK, 256, SMEM_P2>>>(xg, W_hh1, h1, ctr);

    {   // Xg2 = h1 @ W_ih2^T + b_ih2 + b_hh2
        dim3 grid(H4 / 64, MROWS / 128);
        tgemm<<<grid, 256>>>(h1, W_ih2, b_ih2, b_hh2, xg, MROWS, H4, HSZ);
    }
    lstm_persist2<<<NBLK, 256, SMEM_P2>>>(xg, W_hh2, h2, ctr + TSZ);

    {   // outs = h2 @ lin_W^T + lin_b
        dim3 grid((VSZ + 63) / 64, MROWS / 128);
        tgemm<<<grid, 256>>>(h2, lin_W, lin_b, nullptr, out, MROWS, VSZ, HSZ);
    }
}